// round 11
// baseline (speedup 1.0000x reference)
#include <cuda_runtime.h>
#include <math.h>
#include <stdint.h>

#define N_OBJ  100000
#define N_EVT  200000
#define N_EDGE 1000000
#define D      128

// ---------------- scratch (device globals; no allocation) ----------------
__device__ float g_csum [(size_t)N_EVT * D];      // per-event sum of objX rows
__device__ float g_cnt  [N_EVT];                  // edge counts per event
__device__ float g_h1   [(size_t)N_EVT * D];      // relu(...), tf32-rounded
__device__ float g_teff [(size_t)N_OBJ * D];      // per-object sum of himp rows
__device__ float g_gi   [(size_t)N_OBJ * 3 * D];  // x @ Wih^T + bih
__device__ float g_gh   [(size_t)N_OBJ * 3 * D];  // h @ Whh^T + bhh
__device__ float g_wrnd [163840];                 // tf32-rounded weights
__device__ float g_cvec [128];                    // W1b @ ba (fp32)

// CSR bucketing scratch
__device__ int g_offE[N_EVT + 1];
__device__ int g_offO[N_OBJ + 1];
__device__ int g_curE[N_EVT];
__device__ int g_curO[N_OBJ];
__device__ int g_srcE[N_EDGE];    // per-event edge list -> object index
__device__ int g_srcO[N_EDGE];    // per-object edge list -> event index

#define WR_WA   0        // unused slot (layout stability)
#define WR_W1   16384    // fused [W1a | Wc] rows of 256
#define WR_W2   49152
#define WR_WIH  65536
#define WR_WHH  114688

// ---------------- helpers ----------------
__device__ __forceinline__ uint32_t smem_u32(const void* p) {
    uint32_t a;
    asm("{ .reg .u64 t; cvta.to.shared.u64 t, %1; cvt.u32.u64 %0, t; }"
        : "=r"(a) : "l"(p));
    return a;
}

__device__ __forceinline__ uint32_t tf32r(float f) {
    uint32_t o;
    asm("cvt.rna.tf32.f32 %0, %1;" : "=r"(o) : "f"(f));
    return o;
}

__device__ __forceinline__ void cpasync16(uint32_t dst, const void* src, int sz) {
    asm volatile("cp.async.cg.shared.global [%0], [%1], 16, %2;"
                 :: "r"(dst), "l"(src), "r"(sz));
}

__device__ __forceinline__ void ldmx4(uint32_t* r, uint32_t addr) {
    asm volatile(
        "ldmatrix.sync.aligned.x4.m8n8.shared.b16 {%0,%1,%2,%3}, [%4];"
        : "=r"(r[0]), "=r"(r[1]), "=r"(r[2]), "=r"(r[3]) : "r"(addr));
}

__device__ __forceinline__ float sigmoidf_(float x) {
    return 1.0f / (1.0f + expf(-x));
}

__device__ __forceinline__ void mma_tf32(float* c, const uint32_t* a,
                                         const uint32_t* b) {
    asm volatile(
        "mma.sync.aligned.m16n8k8.row.col.f32.tf32.tf32.f32 "
        "{%0,%1,%2,%3}, {%4,%5,%6,%7}, {%8,%9}, {%0,%1,%2,%3};"
        : "+f"(c[0]), "+f"(c[1]), "+f"(c[2]), "+f"(c[3])
        : "r"(a[0]), "r"(a[1]), "r"(a[2]), "r"(a[3]), "r"(b[0]), "r"(b[1]));
}

// ---------------- weight pre-rounding (skips W1 right half) -------------
__global__ void round_weights(const float* __restrict__ W1,
                              const float* __restrict__ W2,
                              const float* __restrict__ Wih,
                              const float* __restrict__ Whh) {
    int i = blockIdx.x * blockDim.x + threadIdx.x;
    if (i < WR_W1 || i >= 163840) return;
    float v;
    if (i < WR_W2) {
        int local = i - WR_W1;
        if ((local & 255) >= 128) return;   // Wc half, filled by wc_kernel
        v = W1[local];
    }
    else if (i < WR_WIH) v = W2 [i - WR_W2];
    else if (i < WR_WHH) v = Wih[i - WR_WIH];
    else                 v = Whh[i - WR_WHH];
    g_wrnd[i] = __uint_as_float(tf32r(v));
}

// ---------------- Wc = W1b @ Wa  (and cvec = W1b @ ba) ------------------
__global__ void wc_kernel(const float* __restrict__ W1,
                          const float* __restrict__ Wa,
                          const float* __restrict__ ba) {
    __shared__ float w1b[128];
    const int n = blockIdx.x;
    const int j = threadIdx.x;
    w1b[j] = W1[n * 256 + 128 + j];
    __syncthreads();
    float s = 0.f;
    #pragma unroll 4
    for (int k = 0; k < 128; k++)
        s = fmaf(w1b[k], Wa[k * 128 + j], s);
    g_wrnd[WR_W1 + n * 256 + 128 + j] = __uint_as_float(tf32r(s));
    if (j == 0) {
        float cs = 0.f;
        for (int k = 0; k < 128; k++) cs = fmaf(w1b[k], ba[k], cs);
        g_cvec[n] = cs;
    }
}

// ---------------- CSR bucketing ------------------------------------------
__global__ void zero_hist() {
    int i = blockIdx.x * blockDim.x + threadIdx.x;
    if (i < N_EVT) g_offE[i] = 0;
    if (i < N_OBJ) g_offO[i] = 0;
}

__global__ void hist_edges(const int* __restrict__ evt_idx,
                           const int* __restrict__ obj_idx) {
    int i = blockIdx.x * blockDim.x + threadIdx.x;
    if (i >= N_EDGE) return;
    atomicAdd(&g_offE[__ldg(evt_idx + i)], 1);
    atomicAdd(&g_offO[__ldg(obj_idx + i)], 1);
}

// grid=2 blocks of 1024: block 0 scans offE (n=N_EVT), block 1 offO (N_OBJ)
__global__ void scan_both() {
    __shared__ int ssum[1024];
    int* data   = blockIdx.x == 0 ? g_offE : g_offO;
    int* cursor = blockIdx.x == 0 ? g_curE : g_curO;
    const int n = blockIdx.x == 0 ? N_EVT : N_OBJ;
    const int tid = threadIdx.x;
    const int chunk = (n + 1023) >> 10;
    const int beg = tid * chunk;
    const int end = min(beg + chunk, n);
    int s = 0;
    for (int i = beg; i < end; i++) s += data[i];
    ssum[tid] = s;
    __syncthreads();
    // Hillis-Steele inclusive scan
    for (int d = 1; d < 1024; d <<= 1) {
        int t = (tid >= d) ? ssum[tid - d] : 0;
        __syncthreads();
        ssum[tid] += t;
        __syncthreads();
    }
    int off = ssum[tid] - s;   // exclusive offset of this chunk
    for (int i = beg; i < end; i++) {
        int v = data[i];
        data[i] = off;
        cursor[i] = off;
        off += v;
    }
    if (tid == 1023) data[n] = ssum[1023];
}

__global__ void permute_edges(const int* __restrict__ evt_idx,
                              const int* __restrict__ obj_idx) {
    int i = blockIdx.x * blockDim.x + threadIdx.x;
    if (i >= N_EDGE) return;
    int ev = __ldg(evt_idx + i);
    int ob = __ldg(obj_idx + i);
    int pE = atomicAdd(&g_curE[ev], 1);
    g_srcE[pE] = ob;
    int pO = atomicAdd(&g_curO[ob], 1);
    g_srcO[pO] = ev;
}

// ---------------- CSR segment sums (one warp per row) -------------------
__global__ void gather_evt(const float* __restrict__ objX) {
    int w = (blockIdx.x * blockDim.x + threadIdx.x) >> 5;
    if (w >= N_EVT) return;
    int lane = threadIdx.x & 31;
    int beg = g_offE[w], end = g_offE[w + 1];
    float4 a0 = make_float4(0.f, 0.f, 0.f, 0.f);
    float4 a1 = make_float4(0.f, 0.f, 0.f, 0.f);
    int i = beg;
    for (; i + 1 < end; i += 2) {
        int o0 = g_srcE[i], o1 = g_srcE[i + 1];
        float4 v0 = *reinterpret_cast<const float4*>(&objX[(size_t)o0 * D + lane * 4]);
        float4 v1 = *reinterpret_cast<const float4*>(&objX[(size_t)o1 * D + lane * 4]);
        a0.x += v0.x; a0.y += v0.y; a0.z += v0.z; a0.w += v0.w;
        a1.x += v1.x; a1.y += v1.y; a1.z += v1.z; a1.w += v1.w;
    }
    if (i < end) {
        int o = g_srcE[i];
        float4 v = *reinterpret_cast<const float4*>(&objX[(size_t)o * D + lane * 4]);
        a0.x += v.x; a0.y += v.y; a0.z += v.z; a0.w += v.w;
    }
    a0.x += a1.x; a0.y += a1.y; a0.z += a1.z; a0.w += a1.w;
    *reinterpret_cast<float4*>(&g_csum[(size_t)w * D + lane * 4]) = a0;
    if (lane == 0) g_cnt[w] = (float)(end - beg);
}

__global__ void gather_obj(const float* __restrict__ himp) {
    int w = (blockIdx.x * blockDim.x + threadIdx.x) >> 5;
    if (w >= N_OBJ) return;
    int lane = threadIdx.x & 31;
    int beg = g_offO[w], end = g_offO[w + 1];
    float4 a0 = make_float4(0.f, 0.f, 0.f, 0.f);
    float4 a1 = make_float4(0.f, 0.f, 0.f, 0.f);
    int i = beg;
    for (; i + 1 < end; i += 2) {
        int e0 = g_srcO[i], e1 = g_srcO[i + 1];
        float4 v0 = *reinterpret_cast<const float4*>(&himp[(size_t)e0 * D + lane * 4]);
        float4 v1 = *reinterpret_cast<const float4*>(&himp[(size_t)e1 * D + lane * 4]);
        a0.x += v0.x; a0.y += v0.y; a0.z += v0.z; a0.w += v0.w;
        a1.x += v1.x; a1.y += v1.y; a1.z += v1.z; a1.w += v1.w;
    }
    if (i < end) {
        int e = g_srcO[i];
        float4 v = *reinterpret_cast<const float4*>(&himp[(size_t)e * D + lane * 4]);
        a0.x += v.x; a0.y += v.y; a0.z += v.z; a0.w += v.w;
    }
    a0.x += a1.x; a0.y += a1.y; a0.z += a1.z; a0.w += a1.w;
    *reinterpret_cast<float4*>(&g_teff[(size_t)w * D + lane * 4]) = a0;
}

// =====================================================================
// tf32 mma.sync GEMM: cp.async 3-stage pipeline, BK=32, ldmatrix loads,
// SW128-style XOR swizzle on dense 128B SMEM rows. (unchanged from R10)
// =====================================================================
#define BK     32
#define STAGES 3
#define STG_W  (128 * 32)
#define GEMM_SMEM (STAGES * STG_W * 2 * 4)    // 98304 bytes

template<int RELU, int CTX, int ACVT, int RNDOUT>
__global__ __launch_bounds__(256, 2)
void gemm_mma(const float* __restrict__ A, const float* __restrict__ A2,
              const float* __restrict__ W,
              const float* __restrict__ bias, float* __restrict__ C,
              int M, int N, int K) {
    extern __shared__ uint32_t sm[];
    uint32_t* As = sm;
    uint32_t* Bs = sm + STAGES * STG_W;
    __shared__ float sinv[128];
    __shared__ float sbeta[128];

    const int tid = threadIdx.x;
    const int wid = tid >> 5;
    const int lane = tid & 31;
    const int gq = lane >> 2;
    const int tg = lane & 3;
    const int warp_m = wid >> 1;
    const int warp_n = wid & 1;
    const int bm = blockIdx.y * 128;
    const int bn = blockIdx.x * 128;

    const uint32_t aAs = smem_u32(As);
    const uint32_t aBs = smem_u32(Bs);

    const int r0 = tid >> 3;
    const int cb = (tid & 7) * 16;
    const int c4f = (tid & 7) * 4;

    uint32_t rowbA[2], swzA[2];
    #pragma unroll
    for (int mt = 0; mt < 2; mt++) {
        int row = warp_m * 32 + mt * 16 + (lane & 15);
        rowbA[mt] = (uint32_t)row * 128;
        swzA[mt] = (uint32_t)(row & 7) << 4;
    }
    const uint32_t hiA = (uint32_t)(lane >> 4) << 4;
    uint32_t rowbB[4], swzB[4];
    #pragma unroll
    for (int j = 0; j < 4; j++) {
        int n = warp_n * 64 + j * 16 + (lane & 7) + (((lane >> 4) & 1) << 3);
        rowbB[j] = (uint32_t)n * 128;
        swzB[j] = (uint32_t)(n & 7) << 4;
    }
    const uint32_t hiB = (lane & 8) ? 16u : 0u;

    float acc[2][8][4];
    #pragma unroll
    for (int i = 0; i < 2; i++)
        #pragma unroll
        for (int j = 0; j < 8; j++)
            #pragma unroll
            for (int q = 0; q < 4; q++) acc[i][j][q] = 0.f;

    const int CHUNKS = K >> 5;

    auto issue = [&](int c) {
        if (c < CHUNKS) {
            const int p = (c % STAGES);
            const int k0 = c * BK + c4f;
            const uint32_t dsw = (uint32_t)cb ^ ((uint32_t)(r0 & 7) << 4);
            #pragma unroll
            for (int h = 0; h < 4; h++) {
                int r = r0 + h * 32;
                const float* srcA;
                if (CTX) {
                    srcA = (k0 < 128)
                         ? &A [(size_t)(bm + r) * 128 + k0]
                         : &A2[(size_t)(bm + r) * 128 + (k0 - 128)];
                } else {
                    srcA = &A[(size_t)(bm + r) * K + k0];
                }
                int szA = (bm + r < M) ? 16 : 0;
                uint32_t doff = (uint32_t)(p * STG_W * 4) + (uint32_t)r * 128 + dsw;
                cpasync16(aAs + doff, srcA, szA);
                cpasync16(aBs + doff, &W[(size_t)(bn + r) * K + k0], 16);
            }
        }
        asm volatile("cp.async.commit_group;");
    };

    float invr[2][2];
    if (CTX) {
        if (tid < 128) {
            int r = bm + tid;
            float cv = (r < M) ? __ldg(&g_cnt[r]) : 1.0f;
            float iv = 1.0f / fmaxf(cv, 1.0f);
            sinv[tid] = iv;
            sbeta[tid] = cv * iv;
        }
    }

    issue(0); issue(1);
    if (CTX) __syncthreads();

    if (CTX) {
        #pragma unroll
        for (int mt = 0; mt < 2; mt++) {
            int row = warp_m * 32 + mt * 16 + gq;
            invr[mt][0] = sinv[row];
            invr[mt][1] = sinv[row + 8];
        }
    }

    for (int c = 0; c < CHUNKS; c++) {
        const int p = (c % STAGES);
        asm volatile("cp.async.wait_group 1;");
        __syncthreads();
        issue(c + 2);

        const bool scale = CTX && (c >= 4);
        const uint32_t stA = aAs + (uint32_t)(p * STG_W) * 4;
        const uint32_t stB = aBs + (uint32_t)(p * STG_W) * 4;
        #pragma unroll
        for (int ks = 0; ks < 4; ks++) {
            const uint32_t kc = (uint32_t)ks * 32;
            uint32_t af[2][4], bf[4][4];
            #pragma unroll
            for (int mt = 0; mt < 2; mt++)
                ldmx4(af[mt], stA + rowbA[mt] + ((kc + hiA) ^ swzA[mt]));
            #pragma unroll
            for (int j = 0; j < 4; j++)
                ldmx4(bf[j], stB + rowbB[j] + ((kc + hiB) ^ swzB[j]));

            if (ACVT) {
                #pragma unroll
                for (int mt = 0; mt < 2; mt++) {
                    float f0 = __uint_as_float(af[mt][0]);
                    float f1 = __uint_as_float(af[mt][1]);
                    float f2 = __uint_as_float(af[mt][2]);
                    float f3 = __uint_as_float(af[mt][3]);
                    if (scale) {
                        f0 *= invr[mt][0]; f1 *= invr[mt][1];
                        f2 *= invr[mt][0]; f3 *= invr[mt][1];
                    }
                    af[mt][0] = tf32r(f0); af[mt][1] = tf32r(f1);
                    af[mt][2] = tf32r(f2); af[mt][3] = tf32r(f3);
                }
            }
            #pragma unroll
            for (int mt = 0; mt < 2; mt++)
                #pragma unroll
                for (int nt = 0; nt < 8; nt++)
                    mma_tf32(acc[mt][nt], af[mt], &bf[nt >> 1][(nt & 1) * 2]);
        }
    }

    // epilogue
    #pragma unroll
    for (int mt = 0; mt < 2; mt++) {
        #pragma unroll
        for (int half = 0; half < 2; half++) {
            int mrow = warp_m * 32 + mt * 16 + gq + half * 8;
            int m = bm + mrow;
            if (m >= M) continue;
            float beta = CTX ? sbeta[mrow] : 0.f;
            #pragma unroll
            for (int nt = 0; nt < 8; nt++) {
                int n = bn + warp_n * 64 + nt * 8 + tg * 2;
                float2 bb = *reinterpret_cast<const float2*>(&bias[n]);
                float2 o;
                o.x = acc[mt][nt][half * 2 + 0] + bb.x;
                o.y = acc[mt][nt][half * 2 + 1] + bb.y;
                if (CTX) {
                    float2 cv = *reinterpret_cast<const float2*>(&g_cvec[n]);
                    o.x = fmaf(beta, cv.x, o.x);
                    o.y = fmaf(beta, cv.y, o.y);
                }
                if (RELU) { o.x = fmaxf(o.x, 0.f); o.y = fmaxf(o.y, 0.f); }
                if (RNDOUT) {
                    o.x = __uint_as_float(tf32r(o.x));
                    o.y = __uint_as_float(tf32r(o.y));
                }
                *reinterpret_cast<float2*>(&C[(size_t)m * N + n]) = o;
            }
        }
    }
}

// ---------------- GRU gate math -----------------------------------------
__global__ void gru_gates(const float* __restrict__ objX, float* __restrict__ out) {
    int gid = blockIdx.x * blockDim.x + threadIdx.x;
    if (gid >= N_OBJ * D) return;
    int r = gid >> 7;
    int d = gid & 127;
    size_t base = (size_t)r * 3 * D + d;
    float ir = g_gi[base], iz = g_gi[base + D], in_ = g_gi[base + 2 * D];
    float hr = g_gh[base], hz = g_gh[base + D], hn  = g_gh[base + 2 * D];
    float h = objX[(size_t)r * D + d];
    float rg = sigmoidf_(ir + hr);
    float z  = sigmoidf_(iz + hz);
    float n  = tanhf(in_ + rg * hn);
    out[(size_t)r * D + d] = (1.0f - z) * n + z * h;
}

// ---------------- launch ------------------------------------------------
extern "C" void kernel_launch(void* const* d_in, const int* in_sizes, int n_in,
                              void* d_out, int out_size) {
    const float* event_X  = (const float*)d_in[0];
    const float* object_X = (const float*)d_in[1];
    const int*   evt_idx  = (const int*)d_in[2];
    const int*   obj_idx  = (const int*)d_in[3];
    const float* Wa  = (const float*)d_in[4];
    const float* ba  = (const float*)d_in[5];
    const float* W1  = (const float*)d_in[6];
    const float* b1  = (const float*)d_in[7];
    const float* W2  = (const float*)d_in[8];
    const float* b2  = (const float*)d_in[9];
    const float* Wih = (const float*)d_in[10];
    const float* Whh = (const float*)d_in[11];
    const float* bih = (const float*)d_in[12];
    const float* bhh = (const float*)d_in[13];

    float* out = (float*)d_out;
    float* out_newobj = out;                       // [N_OBJ, 128]
    float* out_himp   = out + (size_t)N_OBJ * D;   // [N_EVT, 128]

    float* csum  = nullptr; cudaGetSymbolAddress((void**)&csum,  g_csum);
    float* h1    = nullptr; cudaGetSymbolAddress((void**)&h1,    g_h1);
    float* teff  = nullptr; cudaGetSymbolAddress((void**)&teff,  g_teff);
    float* gi    = nullptr; cudaGetSymbolAddress((void**)&gi,    g_gi);
    float* gh    = nullptr; cudaGetSymbolAddress((void**)&gh,    g_gh);
    float* wr    = nullptr; cudaGetSymbolAddress((void**)&wr,    g_wrnd);

    static cudaStream_t sW = nullptr;
    static cudaEvent_t eFork, eW, eGh;
    if (!sW) {
        cudaStreamCreateWithFlags(&sW, cudaStreamNonBlocking);
        cudaEventCreateWithFlags(&eFork, cudaEventDisableTiming);
        cudaEventCreateWithFlags(&eW,   cudaEventDisableTiming);
        cudaEventCreateWithFlags(&eGh,  cudaEventDisableTiming);
        cudaFuncSetAttribute(gemm_mma<0, 0, 1, 0>,
            cudaFuncAttributeMaxDynamicSharedMemorySize, GEMM_SMEM);
        cudaFuncSetAttribute(gemm_mma<1, 1, 1, 1>,
            cudaFuncAttributeMaxDynamicSharedMemorySize, GEMM_SMEM);
        cudaFuncSetAttribute(gemm_mma<0, 0, 0, 0>,
            cudaFuncAttributeMaxDynamicSharedMemorySize, GEMM_SMEM);
    }

    // fork side stream for weight prep + gh GEMM
    cudaEventRecord(eFork, 0);
    cudaStreamWaitEvent(sW, eFork, 0);
    round_weights<<<(163840 + 255) / 256, 256, 0, sW>>>(W1, W2, Wih, Whh);
    wc_kernel<<<128, 128, 0, sW>>>(W1, Wa, ba);
    cudaEventRecord(eW, sW);
    gemm_mma<0, 0, 1, 0><<<dim3(3, (N_OBJ + 127) / 128), 256, GEMM_SMEM, sW>>>(
        object_X, nullptr, wr + WR_WHH, bhh, gh, N_OBJ, 3 * D, D);
    cudaEventRecord(eGh, sW);

    // main: CSR bucketing of edges (indices only)
    zero_hist<<<(N_EVT + 255) / 256, 256>>>();
    hist_edges<<<(N_EDGE + 255) / 256, 256>>>(evt_idx, obj_idx);
    scan_both<<<2, 1024>>>();
    permute_edges<<<(N_EDGE + 255) / 256, 256>>>(evt_idx, obj_idx);

    // per-event segment sum of objX rows -> csum, cnt
    gather_evt<<<(N_EVT * 32 + 255) / 256, 256>>>(object_X);

    // h1 = relu(evX@W1a^T + mean_obj@Wc^T + b1 + beta*cvec)
    cudaStreamWaitEvent(0, eW, 0);
    gemm_mma<1, 1, 1, 1><<<dim3(1, (N_EVT + 127) / 128), 256, GEMM_SMEM>>>(
        event_X, csum, wr + WR_W1, b1, h1, N_EVT, D, 2 * D);

    // h_impulse = h1 @ W2^T + b2 -> output
    gemm_mma<0, 0, 0, 0><<<dim3(1, (N_EVT + 127) / 128), 256, GEMM_SMEM>>>(
        h1, nullptr, wr + WR_W2, b2, out_himp, N_EVT, D, D);

    // per-object segment sum of himp rows -> teff
    gather_obj<<<(N_OBJ * 32 + 255) / 256, 256>>>(out_himp);

    // gi = total_effect @ Wih^T + bih
    gemm_mma<0, 0, 1, 0><<<dim3(3, (N_OBJ + 127) / 128), 256, GEMM_SMEM>>>(
        teff, nullptr, wr + WR_WIH, bih, gi, N_OBJ, 3 * D, D);

    // join gh, then GRU gates -> new_object_X
    cudaStreamWaitEvent(0, eGh, 0);
    gru_gates<<<(N_OBJ * D + 255) / 256, 256>>>(object_X, out_newobj);
}

// round 13
// speedup vs baseline: 1.0564x; 1.0564x over previous
#include <cuda_runtime.h>
#include <math.h>
#include <stdint.h>

#define N_OBJ  100000
#define N_EVT  200000
#define N_EDGE 1000000
#define D      128

// ---------------- scratch (device globals; no allocation) ----------------
__device__ float g_csum [(size_t)N_EVT * D];      // scatter-sum of objX rows
__device__ float g_cnt  [N_EVT];                  // edge counts per event
__device__ float g_h1a  [(size_t)N_EVT * D];      // evX@W1a^T + b1 (fp32)
__device__ float g_h1   [(size_t)N_EVT * D];      // relu(...), tf32-rounded
__device__ float g_teff [(size_t)N_OBJ * D];      // scatter-add into objects
__device__ float g_gi   [(size_t)N_OBJ * 3 * D];  // x @ Wih^T + bih
__device__ float g_gh   [(size_t)N_OBJ * 3 * D];  // h @ Whh^T + bhh
__device__ float g_wrnd [163840];                 // tf32-rounded weights
__device__ float g_cvec [128];                    // W1b @ ba (fp32)

#define WR_WA   0        // unused slot (layout stability)
#define WR_W1   16384    // fused [W1a | Wc] rows of 256
#define WR_W2   49152
#define WR_WIH  65536
#define WR_WHH  114688

// ---------------- helpers ----------------
__device__ __forceinline__ uint32_t smem_u32(const void* p) {
    uint32_t a;
    asm("{ .reg .u64 t; cvta.to.shared.u64 t, %1; cvt.u32.u64 %0, t; }"
        : "=r"(a) : "l"(p));
    return a;
}

__device__ __forceinline__ uint32_t tf32r(float f) {
    uint32_t o;
    asm("cvt.rna.tf32.f32 %0, %1;" : "=r"(o) : "f"(f));
    return o;
}

__device__ __forceinline__ void cpasync16(uint32_t dst, const void* src, int sz) {
    asm volatile("cp.async.cg.shared.global [%0], [%1], 16, %2;"
                 :: "r"(dst), "l"(src), "r"(sz));
}

__device__ __forceinline__ void ldmx4(uint32_t* r, uint32_t addr) {
    asm volatile(
        "ldmatrix.sync.aligned.x4.m8n8.shared.b16 {%0,%1,%2,%3}, [%4];"
        : "=r"(r[0]), "=r"(r[1]), "=r"(r[2]), "=r"(r[3]) : "r"(addr));
}

__device__ __forceinline__ void red4(float* addr, float4 v) {
    asm volatile("red.global.add.v4.f32 [%0], {%1, %2, %3, %4};"
                 :: "l"(addr), "f"(v.x), "f"(v.y), "f"(v.z), "f"(v.w)
                 : "memory");
}

__device__ __forceinline__ float sigmoidf_(float x) {
    return 1.0f / (1.0f + expf(-x));
}

__device__ __forceinline__ void mma_tf32(float* c, const uint32_t* a,
                                         const uint32_t* b) {
    asm volatile(
        "mma.sync.aligned.m16n8k8.row.col.f32.tf32.tf32.f32 "
        "{%0,%1,%2,%3}, {%4,%5,%6,%7}, {%8,%9}, {%0,%1,%2,%3};"
        : "+f"(c[0]), "+f"(c[1]), "+f"(c[2]), "+f"(c[3])
        : "r"(a[0]), "r"(a[1]), "r"(a[2]), "r"(a[3]), "r"(b[0]), "r"(b[1]));
}

// ---------------- weight pre-rounding (skips W1 right half) -------------
__global__ void round_weights(const float* __restrict__ W1,
                              const float* __restrict__ W2,
                              const float* __restrict__ Wih,
                              const float* __restrict__ Whh) {
    int i = blockIdx.x * blockDim.x + threadIdx.x;
    if (i < WR_W1 || i >= 163840) return;
    float v;
    if (i < WR_W2) {
        int local = i - WR_W1;
        if ((local & 255) >= 128) return;   // Wc half, filled by wc_kernel
        v = W1[local];
    }
    else if (i < WR_WIH) v = W2 [i - WR_W2];
    else if (i < WR_WHH) v = Wih[i - WR_WIH];
    else                 v = Whh[i - WR_WHH];
    g_wrnd[i] = __uint_as_float(tf32r(v));
}

// ---------------- Wc = W1b @ Wa  (and cvec = W1b @ ba) ------------------
__global__ void wc_kernel(const float* __restrict__ W1,
                          const float* __restrict__ Wa,
                          const float* __restrict__ ba) {
    __shared__ float w1b[128];
    const int n = blockIdx.x;
    const int j = threadIdx.x;
    w1b[j] = W1[n * 256 + 128 + j];
    __syncthreads();
    float s = 0.f;
    #pragma unroll 4
    for (int k = 0; k < 128; k++)
        s = fmaf(w1b[k], Wa[k * 128 + j], s);
    g_wrnd[WR_W1 + n * 256 + 128 + j] = __uint_as_float(tf32r(s));
    if (j == 0) {
        float cs = 0.f;
        for (int k = 0; k < 128; k++) cs = fmaf(w1b[k], ba[k], cs);
        g_cvec[n] = cs;
    }
}

// ---------------- zeroing ------------------------------------------------
__global__ void zero_csum() {
    int i = blockIdx.x * blockDim.x + threadIdx.x;
    const int n1 = N_EVT * D / 4;
    const int n2 = N_EVT / 4;
    float4 z = make_float4(0.f, 0.f, 0.f, 0.f);
    if (i < n1) reinterpret_cast<float4*>(g_csum)[i] = z;
    if (i < n2) reinterpret_cast<float4*>(g_cnt)[i]  = z;
}

__global__ void zero_teff() {
    int i = blockIdx.x * blockDim.x + threadIdx.x;
    if (i < N_OBJ * D / 4)
        reinterpret_cast<float4*>(g_teff)[i] = make_float4(0.f, 0.f, 0.f, 0.f);
}

// =====================================================================
// tf32 mma.sync GEMM: cp.async 3-stage pipeline, BK=32, ldmatrix loads,
// SW128-style XOR swizzle on dense 128B SMEM rows.
// CTA tile 128x128, 256 threads = 8 warps (4m x 2n), warp 32x64.
// ldw = row stride (floats) of W. A row stride = K.
// SCALEA: scale A rows by 1/max(cnt,1). ADDC: epilogue += Caux + beta*cvec
// (no bias). ACVT: cvt.rna A fragments. RNDOUT: round C to tf32.
// =====================================================================
#define BK     32
#define STAGES 3
#define STG_W  (128 * 32)
#define GEMM_SMEM (STAGES * STG_W * 2 * 4)    // 98304 bytes

template<int RELU, int ACVT, int SCALEA, int ADDC, int RNDOUT>
__global__ __launch_bounds__(256, 2)
void gemm_mma(const float* __restrict__ A,
              const float* __restrict__ W, int ldw,
              const float* __restrict__ bias,
              const float* __restrict__ Caux,
              float* __restrict__ C,
              int M, int N, int K) {
    extern __shared__ uint32_t sm[];
    uint32_t* As = sm;
    uint32_t* Bs = sm + STAGES * STG_W;
    __shared__ float sinv[128];
    __shared__ float sbeta[128];

    const int tid = threadIdx.x;
    const int wid = tid >> 5;
    const int lane = tid & 31;
    const int gq = lane >> 2;
    const int tg = lane & 3;
    const int warp_m = wid >> 1;
    const int warp_n = wid & 1;
    const int bm = blockIdx.y * 128;
    const int bn = blockIdx.x * 128;

    const uint32_t aAs = smem_u32(As);
    const uint32_t aBs = smem_u32(Bs);

    const int r0 = tid >> 3;
    const int cb = (tid & 7) * 16;
    const int c4f = (tid & 7) * 4;

    uint32_t rowbA[2], swzA[2];
    #pragma unroll
    for (int mt = 0; mt < 2; mt++) {
        int row = warp_m * 32 + mt * 16 + (lane & 15);
        rowbA[mt] = (uint32_t)row * 128;
        swzA[mt] = (uint32_t)(row & 7) << 4;
    }
    const uint32_t hiA = (uint32_t)(lane >> 4) << 4;
    uint32_t rowbB[4], swzB[4];
    #pragma unroll
    for (int j = 0; j < 4; j++) {
        int n = warp_n * 64 + j * 16 + (lane & 7) + (((lane >> 4) & 1) << 3);
        rowbB[j] = (uint32_t)n * 128;
        swzB[j] = (uint32_t)(n & 7) << 4;
    }
    const uint32_t hiB = (lane & 8) ? 16u : 0u;

    float acc[2][8][4];
    #pragma unroll
    for (int i = 0; i < 2; i++)
        #pragma unroll
        for (int j = 0; j < 8; j++)
            #pragma unroll
            for (int q = 0; q < 4; q++) acc[i][j][q] = 0.f;

    const int CHUNKS = K >> 5;

    auto issue = [&](int c) {
        if (c < CHUNKS) {
            const int p = (c % STAGES);
            const int k0 = c * BK + c4f;
            const uint32_t dsw = (uint32_t)cb ^ ((uint32_t)(r0 & 7) << 4);
            #pragma unroll
            for (int h = 0; h < 4; h++) {
                int r = r0 + h * 32;
                const float* srcA = &A[(size_t)(bm + r) * K + k0];
                int szA = (bm + r < M) ? 16 : 0;
                uint32_t doff = (uint32_t)(p * STG_W * 4) + (uint32_t)r * 128 + dsw;
                cpasync16(aAs + doff, srcA, szA);
                cpasync16(aBs + doff, &W[(size_t)(bn + r) * ldw + k0], 16);
            }
        }
        asm volatile("cp.async.commit_group;");
    };

    float invr[2][2];
    if (SCALEA) {
        if (tid < 128) {
            int r = bm + tid;
            float cv = (r < M) ? __ldg(&g_cnt[r]) : 1.0f;
            float iv = 1.0f / fmaxf(cv, 1.0f);
            sinv[tid] = iv;
            sbeta[tid] = cv * iv;
        }
    }

    issue(0); issue(1);
    if (SCALEA) __syncthreads();

    if (SCALEA) {
        #pragma unroll
        for (int mt = 0; mt < 2; mt++) {
            int row = warp_m * 32 + mt * 16 + gq;
            invr[mt][0] = sinv[row];
            invr[mt][1] = sinv[row + 8];
        }
    }

    for (int c = 0; c < CHUNKS; c++) {
        const int p = (c % STAGES);
        asm volatile("cp.async.wait_group 1;");
        __syncthreads();
        issue(c + 2);

        const uint32_t stA = aAs + (uint32_t)(p * STG_W) * 4;
        const uint32_t stB = aBs + (uint32_t)(p * STG_W) * 4;
        #pragma unroll
        for (int ks = 0; ks < 4; ks++) {
            const uint32_t kc = (uint32_t)ks * 32;
            uint32_t af[2][4], bf[4][4];
            #pragma unroll
            for (int mt = 0; mt < 2; mt++)
                ldmx4(af[mt], stA + rowbA[mt] + ((kc + hiA) ^ swzA[mt]));
            #pragma unroll
            for (int j = 0; j < 4; j++)
                ldmx4(bf[j], stB + rowbB[j] + ((kc + hiB) ^ swzB[j]));

            if (ACVT) {
                #pragma unroll
                for (int mt = 0; mt < 2; mt++) {
                    float f0 = __uint_as_float(af[mt][0]);
                    float f1 = __uint_as_float(af[mt][1]);
                    float f2 = __uint_as_float(af[mt][2]);
                    float f3 = __uint_as_float(af[mt][3]);
                    if (SCALEA) {
                        f0 *= invr[mt][0]; f1 *= invr[mt][1];
                        f2 *= invr[mt][0]; f3 *= invr[mt][1];
                    }
                    af[mt][0] = tf32r(f0); af[mt][1] = tf32r(f1);
                    af[mt][2] = tf32r(f2); af[mt][3] = tf32r(f3);
                }
            }
            #pragma unroll
            for (int mt = 0; mt < 2; mt++)
                #pragma unroll
                for (int nt = 0; nt < 8; nt++)
                    mma_tf32(acc[mt][nt], af[mt], &bf[nt >> 1][(nt & 1) * 2]);
        }
    }

    // epilogue
    #pragma unroll
    for (int mt = 0; mt < 2; mt++) {
        #pragma unroll
        for (int half = 0; half < 2; half++) {
            int mrow = warp_m * 32 + mt * 16 + gq + half * 8;
            int m = bm + mrow;
            if (m >= M) continue;
            float beta = SCALEA ? sbeta[mrow] : 0.f;
            #pragma unroll
            for (int nt = 0; nt < 8; nt++) {
                int n = bn + warp_n * 64 + nt * 8 + tg * 2;
                float2 o;
                o.x = acc[mt][nt][half * 2 + 0];
                o.y = acc[mt][nt][half * 2 + 1];
                if (ADDC) {
                    float2 ca = *reinterpret_cast<const float2*>(
                        &Caux[(size_t)m * N + n]);
                    float2 cv = *reinterpret_cast<const float2*>(&g_cvec[n]);
                    o.x = o.x + ca.x + beta * cv.x;
                    o.y = o.y + ca.y + beta * cv.y;
                } else {
                    float2 bb = *reinterpret_cast<const float2*>(&bias[n]);
                    o.x += bb.x; o.y += bb.y;
                }
                if (RELU) { o.x = fmaxf(o.x, 0.f); o.y = fmaxf(o.y, 0.f); }
                if (RNDOUT) {
                    o.x = __uint_as_float(tf32r(o.x));
                    o.y = __uint_as_float(tf32r(o.y));
                }
                *reinterpret_cast<float2*>(&C[(size_t)m * N + n]) = o;
            }
        }
    }
}

// ---------------- edge scatter: objX[o] -> sum into events + counts -----
__global__ void scatter_obj_to_evt(const int* __restrict__ obj_idx,
                                   const int* __restrict__ evt_idx,
                                   const float* __restrict__ objX) {
    int gid = blockIdx.x * blockDim.x + threadIdx.x;
    if (gid >= N_EDGE * 32) return;
    int e = gid >> 5;
    int c = gid & 31;
    int o  = __ldg(obj_idx + e);
    int ev = __ldg(evt_idx + e);
    float4 v = *reinterpret_cast<const float4*>(&objX[(size_t)o * D + c * 4]);
    red4(&g_csum[(size_t)ev * D + c * 4], v);
    if (c == 0) atomicAdd(&g_cnt[ev], 1.0f);
}

// ---------------- edge scatter: h_impulse[evt] -> sum into objects ------
__global__ void scatter_evt_to_obj(const int* __restrict__ obj_idx,
                                   const int* __restrict__ evt_idx,
                                   const float* __restrict__ himp) {
    int gid = blockIdx.x * blockDim.x + threadIdx.x;
    if (gid >= N_EDGE * 32) return;
    int e = gid >> 5;
    int c = gid & 31;
    int o  = __ldg(obj_idx + e);
    int ev = __ldg(evt_idx + e);
    float4 v = *reinterpret_cast<const float4*>(&himp[(size_t)ev * D + c * 4]);
    red4(&g_teff[(size_t)o * D + c * 4], v);
}

// ---------------- GRU gate math -----------------------------------------
__global__ void gru_gates(const float* __restrict__ objX, float* __restrict__ out) {
    int gid = blockIdx.x * blockDim.x + threadIdx.x;
    if (gid >= N_OBJ * D) return;
    int r = gid >> 7;
    int d = gid & 127;
    size_t base = (size_t)r * 3 * D + d;
    float ir = g_gi[base], iz = g_gi[base + D], in_ = g_gi[base + 2 * D];
    float hr = g_gh[base], hz = g_gh[base + D], hn  = g_gh[base + 2 * D];
    float h = objX[(size_t)r * D + d];
    float rg = sigmoidf_(ir + hr);
    float z  = sigmoidf_(iz + hz);
    float n  = tanhf(in_ + rg * hn);
    out[(size_t)r * D + d] = (1.0f - z) * n + z * h;
}

// ---------------- launch ------------------------------------------------
extern "C" void kernel_launch(void* const* d_in, const int* in_sizes, int n_in,
                              void* d_out, int out_size) {
    const float* event_X  = (const float*)d_in[0];
    const float* object_X = (const float*)d_in[1];
    const int*   evt_idx  = (const int*)d_in[2];
    const int*   obj_idx  = (const int*)d_in[3];
    const float* Wa  = (const float*)d_in[4];
    const float* ba  = (const float*)d_in[5];
    const float* W1  = (const float*)d_in[6];
    const float* b1  = (const float*)d_in[7];
    const float* W2  = (const float*)d_in[8];
    const float* b2  = (const float*)d_in[9];
    const float* Wih = (const float*)d_in[10];
    const float* Whh = (const float*)d_in[11];
    const float* bih = (const float*)d_in[12];
    const float* bhh = (const float*)d_in[13];

    float* out = (float*)d_out;
    float* out_newobj = out;                       // [N_OBJ, 128]
    float* out_himp   = out + (size_t)N_OBJ * D;   // [N_EVT, 128]

    float* csum  = nullptr; cudaGetSymbolAddress((void**)&csum,  g_csum);
    float* h1a   = nullptr; cudaGetSymbolAddress((void**)&h1a,   g_h1a);
    float* h1    = nullptr; cudaGetSymbolAddress((void**)&h1,    g_h1);
    float* teff  = nullptr; cudaGetSymbolAddress((void**)&teff,  g_teff);
    float* gi    = nullptr; cudaGetSymbolAddress((void**)&gi,    g_gi);
    float* gh    = nullptr; cudaGetSymbolAddress((void**)&gh,    g_gh);
    float* wr    = nullptr; cudaGetSymbolAddress((void**)&wr,    g_wrnd);

    static cudaStream_t sW = nullptr;
    static cudaEvent_t eFork, eH1A, eGh, eZT;
    if (!sW) {
        cudaStreamCreateWithFlags(&sW, cudaStreamNonBlocking);
        cudaEventCreateWithFlags(&eFork, cudaEventDisableTiming);
        cudaEventCreateWithFlags(&eH1A, cudaEventDisableTiming);
        cudaEventCreateWithFlags(&eGh,  cudaEventDisableTiming);
        cudaEventCreateWithFlags(&eZT,  cudaEventDisableTiming);
        cudaFuncSetAttribute(gemm_mma<0, 1, 0, 0, 0>,
            cudaFuncAttributeMaxDynamicSharedMemorySize, GEMM_SMEM);
        cudaFuncSetAttribute(gemm_mma<1, 1, 1, 1, 1>,
            cudaFuncAttributeMaxDynamicSharedMemorySize, GEMM_SMEM);
        cudaFuncSetAttribute(gemm_mma<0, 0, 0, 0, 0>,
            cudaFuncAttributeMaxDynamicSharedMemorySize, GEMM_SMEM);
    }

    // fork side stream: weight prep, evX half-GEMM, gh GEMM, teff zero
    cudaEventRecord(eFork, 0);
    cudaStreamWaitEvent(sW, eFork, 0);
    round_weights<<<(163840 + 255) / 256, 256, 0, sW>>>(W1, W2, Wih, Whh);
    wc_kernel<<<128, 128, 0, sW>>>(W1, Wa, ba);
    // h1a = evX @ W1a^T + b1 (fp32, no relu/round); W1 fused rows of 256
    gemm_mma<0, 1, 0, 0, 0><<<dim3(1, (N_EVT + 127) / 128), 256, GEMM_SMEM, sW>>>(
        event_X, wr + WR_W1, 256, b1, nullptr, h1a, N_EVT, D, D);
    cudaEventRecord(eH1A, sW);
    // gh = object_X @ Whh^T + bhh   (Whh rows have stride 128!)
    gemm_mma<0, 1, 0, 0, 0><<<dim3(3, (N_OBJ + 127) / 128), 256, GEMM_SMEM, sW>>>(
        object_X, wr + WR_WHH, 128, bhh, nullptr, gh, N_OBJ, 3 * D, D);
    cudaEventRecord(eGh, sW);
    zero_teff<<<(N_OBJ * D / 4 + 255) / 256, 256, 0, sW>>>();
    cudaEventRecord(eZT, sW);

    // main: zero csum+cnt -> scatter objX into events
    zero_csum<<<(N_EVT * D / 4 + 255) / 256, 256>>>();
    scatter_obj_to_evt<<<(N_EDGE * 32 + 255) / 256, 256>>>(obj_idx, evt_idx,
                                                           object_X);

    // h1 = relu(h1a + (csum*inv)@Wc^T + beta*cvec), tf32-rounded
    cudaStreamWaitEvent(0, eH1A, 0);
    gemm_mma<1, 1, 1, 1, 1><<<dim3(1, (N_EVT + 127) / 128), 256, GEMM_SMEM>>>(
        csum, wr + WR_W1 + 128, 256, nullptr, h1a, h1, N_EVT, D, D);

    // h_impulse = h1 @ W2^T + b2 -> output
    gemm_mma<0, 0, 0, 0, 0><<<dim3(1, (N_EVT + 127) / 128), 256, GEMM_SMEM>>>(
        h1, wr + WR_W2, 128, b2, nullptr, out_himp, N_EVT, D, D);

    // scatter-add impulses into objects (teff zeroed on side stream)
    cudaStreamWaitEvent(0, eZT, 0);
    scatter_evt_to_obj<<<(N_EDGE * 32 + 255) / 256, 256>>>(obj_idx, evt_idx,
                                                           out_himp);

    // gi = total_effect @ Wih^T + bih   (Wih rows have stride 128!)
    gemm_mma<0, 1, 0, 0, 0><<<dim3(3, (N_OBJ + 127) / 128), 256, GEMM_SMEM>>>(
        teff, wr + WR_WIH, 128, bih, nullptr, gi, N_OBJ, 3 * D, D);

    // join gh, then GRU gates -> new_object_X
    cudaStreamWaitEvent(0, eGh, 0);
    gru_gates<<<(N_OBJ * D + 255) / 256, 256>>>(object_X, out_newobj);
}